// round 6
// baseline (speedup 1.0000x reference)
#include <cuda_runtime.h>
#include <cuda_bf16.h>
#include <cstddef>

// ---------------------------------------------------------------------------
// Problem constants
// ---------------------------------------------------------------------------
#define NN    1024      // nodes
#define BB    32        // batch
#define TT    12        // timesteps
#define HID   64
#define EMB   16
#define HORZ  12

// activation layout everywhere: [node][feat][batch]  (feat*batch contiguous per node)

// ---------------------------------------------------------------------------
// Device scratch (static allocation — no cudaMalloc allowed)
// ---------------------------------------------------------------------------
__device__ float g_A   [NN * NN];                 // adjacency (softmax(relu(E E^T)))
__device__ float g_xT  [NN * TT * BB];            // x transposed: [n][t][b]
__device__ float g_mx  [NN * TT * BB];            // A @ xT
__device__ float g_h1  [NN * TT * HID * BB];      // layer-1 hidden, all t: [n][t][i][b]
__device__ float g_mh1 [NN * TT * HID * BB];      // A @ h1 (all t), filled incrementally
__device__ float g_h2  [NN * HID * BB];           // layer-2 hidden state
__device__ float g_mh  [NN * HID * BB];           // A @ h (layer-2 per step)
__device__ float g_zh  [NN * HID * BB];           // z * h
__device__ float g_mzh [NN * HID * BB];           // A @ (z*h)
__device__ float g_r   [NN * HID * BB];           // reset gate
__device__ float g_zero[HID * BB];                // stays zero (never written)

// generated per-node weights: Wn[n][k][i][o]
__device__ float g_Wg1n[NN * 2 * 65  * 128];
__device__ float g_bg1n[NN * 128];
__device__ float g_Wc1n[NN * 2 * 65  * 64];
__device__ float g_bc1n[NN * 64];
__device__ float g_Wg2n[NN * 2 * 128 * 128];
__device__ float g_bg2n[NN * 128];
__device__ float g_Wc2n[NN * 2 * 128 * 64];
__device__ float g_bc2n[NN * 64];

// ---------------------------------------------------------------------------
// Adjacency: A[n][m] = softmax_m( relu( E[n]·E[m] ) )
// ---------------------------------------------------------------------------
__global__ __launch_bounds__(256) void compute_A_kernel(
    const float* __restrict__ E, float* __restrict__ A)
{
    const int n   = blockIdx.x;
    const int tid = threadIdx.x;
    __shared__ float row[NN];
    __shared__ float red[256];

    float en[EMB];
#pragma unroll
    for (int d = 0; d < EMB; d++) en[d] = E[n * EMB + d];

    for (int m = tid; m < NN; m += 256) {
        float s = 0.f;
#pragma unroll
        for (int d = 0; d < EMB; d++) s += en[d] * E[m * EMB + d];
        row[m] = fmaxf(s, 0.f);
    }
    __syncthreads();

    float mx = -1e30f;
    for (int m = tid; m < NN; m += 256) mx = fmaxf(mx, row[m]);
    red[tid] = mx; __syncthreads();
    for (int s = 128; s > 0; s >>= 1) { if (tid < s) red[tid] = fmaxf(red[tid], red[tid + s]); __syncthreads(); }
    mx = red[0]; __syncthreads();

    float sum = 0.f;
    for (int m = tid; m < NN; m += 256) { float e = expf(row[m] - mx); row[m] = e; sum += e; }
    red[tid] = sum; __syncthreads();
    for (int s = 128; s > 0; s >>= 1) { if (tid < s) red[tid] += red[tid + s]; __syncthreads(); }
    const float inv = 1.f / red[0];
    __syncthreads();

    for (int m = tid; m < NN; m += 256) A[n * NN + m] = row[m] * inv;
}

// ---------------------------------------------------------------------------
// x [B,T,N,1] -> xT [n][t][b]
// ---------------------------------------------------------------------------
__global__ void transpose_x_kernel(const float* __restrict__ x, float* __restrict__ xT)
{
    int idx = blockIdx.x * 256 + threadIdx.x;
    if (idx >= BB * TT * NN) return;
    int n  = idx & (NN - 1);
    int bt = idx >> 10;
    int t  = bt % TT;
    int b  = bt / TT;
    xT[n * (TT * BB) + t * BB + b] = x[idx];
}

// ---------------------------------------------------------------------------
// Per-node weight generation: Wn[n][idx] = sum_d E[n][d] * Wp[d][idx]
// grid: (ceil(total/256), 32 node-groups), block 256
// ---------------------------------------------------------------------------
__global__ __launch_bounds__(256) void gen_w_kernel(
    const float* __restrict__ Wp, const float* __restrict__ E,
    float* __restrict__ Wn, int total)
{
    __shared__ float se[32 * EMB];
    const int n0 = blockIdx.y * 32;
    for (int i = threadIdx.x; i < 32 * EMB; i += 256) se[i] = E[n0 * EMB + i];
    __syncthreads();

    int idx = blockIdx.x * 256 + threadIdx.x;
    if (idx >= total) return;

    float wp[EMB];
#pragma unroll
    for (int d = 0; d < EMB; d++) wp[d] = Wp[d * total + idx];

#pragma unroll 4
    for (int nn = 0; nn < 32; nn++) {
        float a = 0.f;
#pragma unroll
        for (int d = 0; d < EMB; d++) a += se[nn * EMB + d] * wp[d];
        Wn[(n0 + nn) * total + idx] = a;
    }
}

// ---------------------------------------------------------------------------
// SGEMM: Y[1024 x ncols] = A[1024 x 1024] @ X[1024 x ncols]
// 128x128 block tile, K-tile 8, 8x8 per thread, 256 threads.
// ncols must be a multiple of 128 (call sites: 384, 2048).
// ldx/ldy: row strides of X/Y (floats).
// ---------------------------------------------------------------------------
__global__ __launch_bounds__(256) void sgemm128(
    const float* __restrict__ A, const float* __restrict__ X,
    float* __restrict__ Y, int ncols, int ldx, int ldy)
{
    __shared__ float As[8][128];
    __shared__ float Xs[8][128];

    const int tid     = threadIdx.x;
    const int rowbase = blockIdx.y * 128;
    const int colbase = blockIdx.x * 128;

    const int arow = tid >> 1;
    const int acol = (tid & 1) << 2;
    const int xrow = tid >> 5;
    const int xcol = (tid & 31) << 2;
    const int ty   = tid >> 4;   // 0..15
    const int tx   = tid & 15;   // 0..15

    float acc[8][8];
#pragma unroll
    for (int i = 0; i < 8; i++)
#pragma unroll
        for (int j = 0; j < 8; j++) acc[i][j] = 0.f;

    for (int k0 = 0; k0 < 1024; k0 += 8) {
        float4 av = *reinterpret_cast<const float4*>(&A[(rowbase + arow) * 1024 + k0 + acol]);
        As[acol + 0][arow] = av.x;
        As[acol + 1][arow] = av.y;
        As[acol + 2][arow] = av.z;
        As[acol + 3][arow] = av.w;

        float4 xv = *reinterpret_cast<const float4*>(&X[(size_t)(k0 + xrow) * ldx + colbase + xcol]);
        *reinterpret_cast<float4*>(&Xs[xrow][xcol]) = xv;
        __syncthreads();

#pragma unroll
        for (int kk = 0; kk < 8; kk++) {
            float4 a0 = *reinterpret_cast<const float4*>(&As[kk][ty * 8]);
            float4 a1 = *reinterpret_cast<const float4*>(&As[kk][ty * 8 + 4]);
            float4 b0 = *reinterpret_cast<const float4*>(&Xs[kk][tx * 8]);
            float4 b1 = *reinterpret_cast<const float4*>(&Xs[kk][tx * 8 + 4]);
            float a[8] = {a0.x, a0.y, a0.z, a0.w, a1.x, a1.y, a1.z, a1.w};
            float b[8] = {b0.x, b0.y, b0.z, b0.w, b1.x, b1.y, b1.z, b1.w};
#pragma unroll
            for (int i = 0; i < 8; i++)
#pragma unroll
                for (int j = 0; j < 8; j++) acc[i][j] += a[i] * b[j];
        }
        __syncthreads();
    }

#pragma unroll
    for (int i = 0; i < 8; i++) {
        size_t r = (size_t)(rowbase + ty * 8 + i);
        float4 v0 = make_float4(acc[i][0], acc[i][1], acc[i][2], acc[i][3]);
        float4 v1 = make_float4(acc[i][4], acc[i][5], acc[i][6], acc[i][7]);
        *reinterpret_cast<float4*>(&Y[r * ldy + colbase + tx * 8])     = v0;
        *reinterpret_cast<float4*>(&Y[r * ldy + colbase + tx * 8 + 4]) = v1;
    }
}

// ---------------------------------------------------------------------------
// Gate apply: per node n, out[b,o] = sum_{k,i} xg[k,i,b] * W[n,k,i,o] + bias
// zr = sigmoid(out); o<64 -> write zh = z * h ; o>=64 -> write r.
// Sources (node-stride variants; stride 0 => zero buffer):
//   k=0:  i<Cix from sX0, else sH0     k=1:  i<Cix from sX1, else sH1
// block = node, 128 threads (one per output column o)
// ---------------------------------------------------------------------------
__global__ __launch_bounds__(128) void gate_apply_kernel(
    const float* __restrict__ sX0, int stx0,
    const float* __restrict__ sH0, int sth0,
    const float* __restrict__ sX1, int stx1,
    const float* __restrict__ sH1, int sth1,
    const float* __restrict__ W, const float* __restrict__ bias,
    float* __restrict__ zh, float* __restrict__ rout, int Cix)
{
    const int n  = blockIdx.x;
    const int o  = threadIdx.x;             // 0..127
    const int Ci = Cix + HID;

    __shared__ float s[2 * 128 * BB];       // [k][i][b], 32 KB max

    const int total = 2 * Ci * BB;
    for (int idx = threadIdx.x; idx < total; idx += 128) {
        int b  = idx & 31;
        int ki = idx >> 5;
        int k  = (ki >= Ci) ? 1 : 0;
        int i  = ki - (k ? Ci : 0);
        float v;
        if (i < Cix) v = k ? sX1[(size_t)n * stx1 + i * BB + b]
                           : sX0[(size_t)n * stx0 + i * BB + b];
        else {
            int ih = i - Cix;
            v = k ? sH1[(size_t)n * sth1 + ih * BB + b]
                  : sH0[(size_t)n * sth0 + ih * BB + b];
        }
        s[idx] = v;
    }
    __syncthreads();

    float acc[BB];
#pragma unroll
    for (int b = 0; b < BB; b++) acc[b] = 0.f;

    const float* Wn = W + (size_t)n * 2 * Ci * 128;
    for (int k = 0; k < 2; k++) {
        const float* Wk = Wn + k * Ci * 128;
        const float* sk = s  + k * Ci * BB;
        for (int i = 0; i < Ci; i++) {
            float w = Wk[i * 128 + o];
            const float4* sp = reinterpret_cast<const float4*>(sk + i * BB);
#pragma unroll
            for (int j = 0; j < 8; j++) {
                float4 v = sp[j];
                acc[4 * j + 0] += v.x * w;
                acc[4 * j + 1] += v.y * w;
                acc[4 * j + 2] += v.z * w;
                acc[4 * j + 3] += v.w * w;
            }
        }
    }

    const float bb = bias[n * 128 + o];
    if (o < HID) {
        const float* hpart = s + Cix * BB + o * BB;   // k=0, h segment, row o
        float* zp = zh + ((size_t)n * HID + o) * BB;
#pragma unroll
        for (int b = 0; b < BB; b++) {
            float g = 1.f / (1.f + __expf(-(acc[b] + bb)));
            zp[b] = g * hpart[b];
        }
    } else {
        const int oo = o - HID;
        float* rp = rout + ((size_t)n * HID + oo) * BB;
#pragma unroll
        for (int b = 0; b < BB; b++)
            rp[b] = 1.f / (1.f + __expf(-(acc[b] + bb)));
    }
}

// ---------------------------------------------------------------------------
// Candidate apply + GRU update:
//   hc = tanh(sum_{k,i} xg[k,i,b] * Wc[n,k,i,o] + bias)
//   hnew = r * hold + (1-r) * hc
// block = node, 64 threads (one per output column o)
// ---------------------------------------------------------------------------
__global__ __launch_bounds__(64) void cand_apply_kernel(
    const float* __restrict__ sX0, int stx0,
    const float* __restrict__ sH0, int sth0,
    const float* __restrict__ sX1, int stx1,
    const float* __restrict__ sH1, int sth1,
    const float* __restrict__ W, const float* __restrict__ bias,
    const float* __restrict__ rbuf,
    const float* __restrict__ hold, int sthold,
    float* __restrict__ hnew, int sthnew, int Cix)
{
    const int n  = blockIdx.x;
    const int o  = threadIdx.x;             // 0..63
    const int Ci = Cix + HID;

    __shared__ float s[2 * 128 * BB];

    const int total = 2 * Ci * BB;
    for (int idx = threadIdx.x; idx < total; idx += 64) {
        int b  = idx & 31;
        int ki = idx >> 5;
        int k  = (ki >= Ci) ? 1 : 0;
        int i  = ki - (k ? Ci : 0);
        float v;
        if (i < Cix) v = k ? sX1[(size_t)n * stx1 + i * BB + b]
                           : sX0[(size_t)n * stx0 + i * BB + b];
        else {
            int ih = i - Cix;
            v = k ? sH1[(size_t)n * sth1 + ih * BB + b]
                  : sH0[(size_t)n * sth0 + ih * BB + b];
        }
        s[idx] = v;
    }
    __syncthreads();

    float acc[BB];
#pragma unroll
    for (int b = 0; b < BB; b++) acc[b] = 0.f;

    const float* Wn = W + (size_t)n * 2 * Ci * HID;
    for (int k = 0; k < 2; k++) {
        const float* Wk = Wn + k * Ci * HID;
        const float* sk = s  + k * Ci * BB;
        for (int i = 0; i < Ci; i++) {
            float w = Wk[i * HID + o];
            const float4* sp = reinterpret_cast<const float4*>(sk + i * BB);
#pragma unroll
            for (int j = 0; j < 8; j++) {
                float4 v = sp[j];
                acc[4 * j + 0] += v.x * w;
                acc[4 * j + 1] += v.y * w;
                acc[4 * j + 2] += v.z * w;
                acc[4 * j + 3] += v.w * w;
            }
        }
    }

    const float bb = bias[n * HID + o];
    const float* rp = rbuf + ((size_t)n * HID + o) * BB;
    const float* hp = hold + (size_t)n * sthold + o * BB;
    float* out = hnew + (size_t)n * sthnew + o * BB;
#pragma unroll
    for (int b = 0; b < BB; b++) {
        float hc = tanhf(acc[b] + bb);
        float r  = rp[b];
        out[b] = r * hp[b] + (1.f - r) * hc;
    }
}

// ---------------------------------------------------------------------------
// Output head: out[b,hor,n] = h2[n,:,b] . Wout[hor,:] + bout[hor]
// ---------------------------------------------------------------------------
__global__ __launch_bounds__(384) void out_kernel(
    const float* __restrict__ h2, const float* __restrict__ Wout,
    const float* __restrict__ bout, float* __restrict__ out)
{
    const int n = blockIdx.x;
    __shared__ float sh[HID * BB];
    for (int idx = threadIdx.x; idx < HID * BB; idx += 384)
        sh[idx] = h2[(size_t)n * HID * BB + idx];
    __syncthreads();

    int p = threadIdx.x;                    // 0..383 = b*12 + hor
    int b = p / HORZ, hor = p % HORZ;
    float a = bout[hor];
#pragma unroll
    for (int j = 0; j < HID; j++) a += sh[j * BB + b] * Wout[hor * HID + j];
    out[(b * HORZ + hor) * NN + n] = a;
}

// ---------------------------------------------------------------------------
// Host orchestration
// ---------------------------------------------------------------------------
static float* sym_addr(const void* symbol)
{
    void* p = nullptr;
    cudaGetSymbolAddress(&p, symbol);
    return reinterpret_cast<float*>(p);
}

extern "C" void kernel_launch(void* const* d_in, const int* in_sizes, int n_in,
                              void* d_out, int out_size)
{
    (void)in_sizes; (void)n_in; (void)out_size;
    const float* x    = (const float*)d_in[0];
    const float* E    = (const float*)d_in[1];
    const float* Wg1  = (const float*)d_in[2];
    const float* bg1  = (const float*)d_in[3];
    const float* Wc1  = (const float*)d_in[4];
    const float* bc1  = (const float*)d_in[5];
    const float* Wg2  = (const float*)d_in[6];
    const float* bg2  = (const float*)d_in[7];
    const float* Wc2  = (const float*)d_in[8];
    const float* bc2  = (const float*)d_in[9];
    const float* Wout = (const float*)d_in[10];
    const float* bout = (const float*)d_in[11];
    float* out = (float*)d_out;

    float* A    = sym_addr(g_A);
    float* xT   = sym_addr(g_xT);
    float* mx   = sym_addr(g_mx);
    float* h1   = sym_addr(g_h1);
    float* mh1  = sym_addr(g_mh1);
    float* h2   = sym_addr(g_h2);
    float* mh   = sym_addr(g_mh);
    float* zh   = sym_addr(g_zh);
    float* mzh  = sym_addr(g_mzh);
    float* rb   = sym_addr(g_r);
    float* zero = sym_addr(g_zero);
    float* wg1n = sym_addr(g_Wg1n);
    float* bg1n = sym_addr(g_bg1n);
    float* wc1n = sym_addr(g_Wc1n);
    float* bc1n = sym_addr(g_bc1n);
    float* wg2n = sym_addr(g_Wg2n);
    float* bg2n = sym_addr(g_bg2n);
    float* wc2n = sym_addr(g_Wc2n);
    float* bc2n = sym_addr(g_bc2n);

    const int HB  = HID * BB;               // 2048
    const int LD1 = TT * HB;                // 24576 (h1 / mh1 row stride)

    // ---- precompute ----
    compute_A_kernel<<<NN, 256>>>(E, A);
    transpose_x_kernel<<<(BB * TT * NN + 255) / 256, 256>>>(x, xT);

    gen_w_kernel<<<dim3((2 * 65 * 128 + 255) / 256, 32), 256>>>(Wg1, E, wg1n, 2 * 65 * 128);
    gen_w_kernel<<<dim3(1, 32), 256>>>(bg1, E, bg1n, 128);
    gen_w_kernel<<<dim3((2 * 65 * 64 + 255) / 256, 32), 256>>>(Wc1, E, wc1n, 2 * 65 * 64);
    gen_w_kernel<<<dim3(1, 32), 256>>>(bc1, E, bc1n, 64);
    gen_w_kernel<<<dim3((2 * 128 * 128) / 256, 32), 256>>>(Wg2, E, wg2n, 2 * 128 * 128);
    gen_w_kernel<<<dim3(1, 32), 256>>>(bg2, E, bg2n, 128);
    gen_w_kernel<<<dim3((2 * 128 * 64) / 256, 32), 256>>>(Wc2, E, wc2n, 2 * 128 * 64);
    gen_w_kernel<<<dim3(1, 32), 256>>>(bc2, E, bc2n, 64);

    // mixed x for layer 1 (all timesteps at once): [N, T*B]
    sgemm128<<<dim3((TT * BB) / 128, 8), 256>>>(A, xT, mx, TT * BB, TT * BB, TT * BB);

    // ---- layer 1 ----
    // A @ h1[t-1] is written straight into the mh1 slab (slice t-1), so the
    // per-step mixing doubles as the layer-2 input mixing; only the t=11
    // slice needs a separate GEMM after the loop.
    for (int t = 0; t < TT; t++) {
        const float *hp, *mhp, *mzhp;
        int shp, smh, smzh;
        if (t == 0) { hp = zero; shp = 0; mhp = zero; smh = 0; }
        else {
            hp = h1 + (t - 1) * HB; shp = LD1;
            float* mdst = mh1 + (t - 1) * HB;
            sgemm128<<<dim3(HB / 128, 8), 256>>>(A, hp, mdst, HB, LD1, LD1);
            mhp = mdst; smh = LD1;
        }
        gate_apply_kernel<<<NN, 128>>>(xT + t * BB, TT * BB, hp, shp,
                                       mx + t * BB, TT * BB, mhp, smh,
                                       wg1n, bg1n, zh, rb, 1);
        if (t == 0) { mzhp = zero; smzh = 0; }
        else {
            sgemm128<<<dim3(HB / 128, 8), 256>>>(A, zh, mzh, HB, HB, HB);
            mzhp = mzh; smzh = HB;
        }
        cand_apply_kernel<<<NN, 64>>>(xT + t * BB, TT * BB, zh, HB,
                                      mx + t * BB, TT * BB, mzhp, smzh,
                                      wc1n, bc1n, rb, hp, shp,
                                      h1 + t * HB, LD1, 1);
    }
    // missing slice: A @ h1[11] -> mh1 slice 11
    sgemm128<<<dim3(HB / 128, 8), 256>>>(A, h1 + (TT - 1) * HB,
                                         mh1 + (TT - 1) * HB, HB, LD1, LD1);

    // ---- layer 2 ----
    for (int t = 0; t < TT; t++) {
        const float* x0 = h1  + t * HB;
        const float* x1 = mh1 + t * HB;
        const float *hp, *mhp, *mzhp;
        int shp, smh, smzh;
        if (t == 0) { hp = zero; shp = 0; mhp = zero; smh = 0; }
        else {
            hp = h2; shp = HB;
            sgemm128<<<dim3(HB / 128, 8), 256>>>(A, h2, mh, HB, HB, HB);
            mhp = mh; smh = HB;
        }
        gate_apply_kernel<<<NN, 128>>>(x0, LD1, hp, shp,
                                       x1, LD1, mhp, smh,
                                       wg2n, bg2n, zh, rb, HID);
        if (t == 0) { mzhp = zero; smzh = 0; }
        else {
            sgemm128<<<dim3(HB / 128, 8), 256>>>(A, zh, mzh, HB, HB, HB);
            mzhp = mzh; smzh = HB;
        }
        cand_apply_kernel<<<NN, 64>>>(x0, LD1, zh, HB,
                                      x1, LD1, mzhp, smzh,
                                      wc2n, bc2n, rb, hp, shp,
                                      h2, HB, HID);
    }

    // ---- output head ----
    out_kernel<<<NN, 384>>>(h2, Wout, bout, out);
}

// round 10
// speedup vs baseline: 1.0317x; 1.0317x over previous
#include <cuda_runtime.h>
#include <cuda_bf16.h>
#include <cstddef>

// ---------------------------------------------------------------------------
// Problem constants
// ---------------------------------------------------------------------------
#define NN    1024      // nodes
#define BB    32        // batch
#define TT    12        // timesteps
#define HID   64
#define EMB   16
#define HORZ  12

// activation layout everywhere: [node][feat][batch]  (feat*batch contiguous per node)

// ---------------------------------------------------------------------------
// Device scratch (static allocation — no cudaMalloc allowed)
// ---------------------------------------------------------------------------
__device__ float g_A   [NN * NN];                 // adjacency (softmax(relu(E E^T)))
__device__ float g_xT  [NN * TT * BB];            // x transposed: [n][t][b]
__device__ float g_mx  [NN * TT * BB];            // A @ xT
__device__ float g_h1  [NN * TT * HID * BB];      // layer-1 hidden, all t: [n][t][i][b]
__device__ float g_mh1 [NN * TT * HID * BB];      // A @ h1 (all t), filled incrementally
__device__ float g_h2  [NN * HID * BB];           // layer-2 hidden state
__device__ float g_mh  [NN * HID * BB];           // A @ h (layer-2 per step)
__device__ float g_zh  [NN * HID * BB];           // z * h
__device__ float g_mzh [NN * HID * BB];           // A @ (z*h)
__device__ float g_r   [NN * HID * BB];           // reset gate
__device__ float g_zero[HID * BB];                // stays zero (never written)

// generated per-node weights: Wn[n][k][i][o]
__device__ float g_Wg1n[NN * 2 * 65  * 128];
__device__ float g_bg1n[NN * 128];
__device__ float g_Wc1n[NN * 2 * 65  * 64];
__device__ float g_bc1n[NN * 64];
__device__ float g_Wg2n[NN * 2 * 128 * 128];
__device__ float g_bg2n[NN * 128];
__device__ float g_Wc2n[NN * 2 * 128 * 64];
__device__ float g_bc2n[NN * 64];

// ---------------------------------------------------------------------------
// Adjacency: A[n][m] = softmax_m( relu( E[n]·E[m] ) )
// ---------------------------------------------------------------------------
__global__ __launch_bounds__(256) void compute_A_kernel(
    const float* __restrict__ E, float* __restrict__ A)
{
    const int n   = blockIdx.x;
    const int tid = threadIdx.x;
    __shared__ float row[NN];
    __shared__ float red[256];

    float en[EMB];
#pragma unroll
    for (int d = 0; d < EMB; d++) en[d] = E[n * EMB + d];

    for (int m = tid; m < NN; m += 256) {
        float s = 0.f;
#pragma unroll
        for (int d = 0; d < EMB; d++) s += en[d] * E[m * EMB + d];
        row[m] = fmaxf(s, 0.f);
    }
    __syncthreads();

    float mx = -1e30f;
    for (int m = tid; m < NN; m += 256) mx = fmaxf(mx, row[m]);
    red[tid] = mx; __syncthreads();
    for (int s = 128; s > 0; s >>= 1) { if (tid < s) red[tid] = fmaxf(red[tid], red[tid + s]); __syncthreads(); }
    mx = red[0]; __syncthreads();

    float sum = 0.f;
    for (int m = tid; m < NN; m += 256) { float e = expf(row[m] - mx); row[m] = e; sum += e; }
    red[tid] = sum; __syncthreads();
    for (int s = 128; s > 0; s >>= 1) { if (tid < s) red[tid] += red[tid + s]; __syncthreads(); }
    const float inv = 1.f / red[0];
    __syncthreads();

    for (int m = tid; m < NN; m += 256) A[n * NN + m] = row[m] * inv;
}

// ---------------------------------------------------------------------------
// x [B,T,N,1] -> xT [n][t][b]
// ---------------------------------------------------------------------------
__global__ void transpose_x_kernel(const float* __restrict__ x, float* __restrict__ xT)
{
    int idx = blockIdx.x * 256 + threadIdx.x;
    if (idx >= BB * TT * NN) return;
    int n  = idx & (NN - 1);
    int bt = idx >> 10;
    int t  = bt % TT;
    int b  = bt / TT;
    xT[n * (TT * BB) + t * BB + b] = x[idx];
}

// ---------------------------------------------------------------------------
// Per-node weight generation: Wn[n][idx] = sum_d E[n][d] * Wp[d][idx]
// ---------------------------------------------------------------------------
__global__ __launch_bounds__(256) void gen_w_kernel(
    const float* __restrict__ Wp, const float* __restrict__ E,
    float* __restrict__ Wn, int total)
{
    __shared__ float se[32 * EMB];
    const int n0 = blockIdx.y * 32;
    for (int i = threadIdx.x; i < 32 * EMB; i += 256) se[i] = E[n0 * EMB + i];
    __syncthreads();

    int idx = blockIdx.x * 256 + threadIdx.x;
    if (idx >= total) return;

    float wp[EMB];
#pragma unroll
    for (int d = 0; d < EMB; d++) wp[d] = Wp[d * total + idx];

#pragma unroll 4
    for (int nn = 0; nn < 32; nn++) {
        float a = 0.f;
#pragma unroll
        for (int d = 0; d < EMB; d++) a += se[nn * EMB + d] * wp[d];
        Wn[(n0 + nn) * total + idx] = a;
    }
}

// ---------------------------------------------------------------------------
// SGEMM via packed fp32x2 FMA (fma.rn.f32x2 — 2 IEEE fp32 FMAs per issue):
//   Y[1024 x ncols] = A[1024 x 1024] @ X[1024 x ncols]
// 128x128 tile, K-tile 16, 256 threads, 8x8 per thread (32 f32x2 accumulators).
// A tile stored SPLATTED in smem ((a,a) pairs) so both FMA2 operands are
// direct 64-bit loads. Double-buffered smem + register prefetch: one
// __syncthreads per K-tile. ncols multiple of 128; ldx/ldy row strides.
// ---------------------------------------------------------------------------
#define FMA2(c, a, b) asm("fma.rn.f32x2 %0, %1, %2, %0;" : "+l"(c) : "l"(a), "l"(b))

__global__ __launch_bounds__(256, 2) void sgemm_f32x2(
    const float* __restrict__ A, const float* __restrict__ X,
    float* __restrict__ Y, int ldx, int ldy)
{
    __shared__ float As2[2][16][256];   // [buf][k][2*m], splatted pairs (32 KB)
    __shared__ float Xs [2][16][128];   // [buf][k][col]                 (16 KB)

    const int tid     = threadIdx.x;
    const int rowbase = blockIdx.y * 128;
    const int colbase = blockIdx.x * 128;

    const int arow = tid >> 1;          // 0..127  (m within tile)
    const int acol = (tid & 1) << 3;    // 0 or 8  (k offset)
    const int xrow = tid >> 4;          // 0..15   (k within tile)
    const int xcol = (tid & 15) << 3;   // 0..120  (col, 8 wide)
    const int ty   = tid >> 4;          // 0..15   (m group)
    const int tx   = tid & 15;          // 0..15   (col group)

    const float* Aptr = A + (size_t)(rowbase + arow) * 1024 + acol;
    const float* Xptr = X + (size_t)xrow * ldx + colbase + xcol;

    unsigned long long acc[8][4];
#pragma unroll
    for (int i = 0; i < 8; i++)
#pragma unroll
        for (int j = 0; j < 4; j++) acc[i][j] = 0ULL;   // (0.f, 0.f)

    // ---- prologue: tile 0 -> buf 0 ----
    {
        float4 a0 = *reinterpret_cast<const float4*>(Aptr);
        float4 a1 = *reinterpret_cast<const float4*>(Aptr + 4);
        float4 x0 = *reinterpret_cast<const float4*>(Xptr);
        float4 x1 = *reinterpret_cast<const float4*>(Xptr + 4);
        float av[8] = {a0.x, a0.y, a0.z, a0.w, a1.x, a1.y, a1.z, a1.w};
#pragma unroll
        for (int c = 0; c < 8; c++)
            *reinterpret_cast<float2*>(&As2[0][acol + c][2 * arow]) = make_float2(av[c], av[c]);
        *reinterpret_cast<float4*>(&Xs[0][xrow][xcol])     = x0;
        *reinterpret_cast<float4*>(&Xs[0][xrow][xcol + 4]) = x1;
    }
    __syncthreads();

    int buf = 0;
    for (int k0 = 0; k0 < 1024; k0 += 16) {
        const bool has_next = (k0 + 16) < 1024;
        float4 na0, na1, nx0, nx1;
        if (has_next) {
            na0 = *reinterpret_cast<const float4*>(Aptr + k0 + 16);
            na1 = *reinterpret_cast<const float4*>(Aptr + k0 + 20);
            nx0 = *reinterpret_cast<const float4*>(Xptr + (size_t)(k0 + 16) * ldx);
            nx1 = *reinterpret_cast<const float4*>(Xptr + (size_t)(k0 + 16) * ldx + 4);
        }

#pragma unroll
        for (int kk = 0; kk < 16; kk++) {
            const ulonglong2* ap = reinterpret_cast<const ulonglong2*>(&As2[buf][kk][ty * 16]);
            const ulonglong2* bp = reinterpret_cast<const ulonglong2*>(&Xs[buf][kk][tx * 8]);
            ulonglong2 av0 = ap[0], av1 = ap[1], av2 = ap[2], av3 = ap[3];
            ulonglong2 bv0 = bp[0], bv1 = bp[1];
            unsigned long long a2[8] = {av0.x, av0.y, av1.x, av1.y,
                                        av2.x, av2.y, av3.x, av3.y};
            unsigned long long b2[4] = {bv0.x, bv0.y, bv1.x, bv1.y};
#pragma unroll
            for (int i = 0; i < 8; i++)
#pragma unroll
                for (int j = 0; j < 4; j++) FMA2(acc[i][j], a2[i], b2[j]);
        }

        if (has_next) {
            const int nb = buf ^ 1;
            float av[8] = {na0.x, na0.y, na0.z, na0.w, na1.x, na1.y, na1.z, na1.w};
#pragma unroll
            for (int c = 0; c < 8; c++)
                *reinterpret_cast<float2*>(&As2[nb][acol + c][2 * arow]) = make_float2(av[c], av[c]);
            *reinterpret_cast<float4*>(&Xs[nb][xrow][xcol])     = nx0;
            *reinterpret_cast<float4*>(&Xs[nb][xrow][xcol + 4]) = nx1;
        }
        __syncthreads();
        buf ^= 1;
    }

    // ---- epilogue: acc[i][0..3] is 8 consecutive fp32 for cols tx*8.. ----
#pragma unroll
    for (int i = 0; i < 8; i++) {
        size_t r = (size_t)(rowbase + ty * 8 + i);
        float* dst = &Y[r * ldy + colbase + tx * 8];
        *reinterpret_cast<float4*>(dst)     = *reinterpret_cast<const float4*>(&acc[i][0]);
        *reinterpret_cast<float4*>(dst + 4) = *reinterpret_cast<const float4*>(&acc[i][2]);
    }
}

// ---------------------------------------------------------------------------
// Gate apply: per node n, out[b,o] = sum_{k,i} xg[k,i,b] * W[n,k,i,o] + bias
// zr = sigmoid(out); o<64 -> write zh = z * h ; o>=64 -> write r.
// ---------------------------------------------------------------------------
__global__ __launch_bounds__(128) void gate_apply_kernel(
    const float* __restrict__ sX0, int stx0,
    const float* __restrict__ sH0, int sth0,
    const float* __restrict__ sX1, int stx1,
    const float* __restrict__ sH1, int sth1,
    const float* __restrict__ W, const float* __restrict__ bias,
    float* __restrict__ zh, float* __restrict__ rout, int Cix)
{
    const int n  = blockIdx.x;
    const int o  = threadIdx.x;             // 0..127
    const int Ci = Cix + HID;

    __shared__ float s[2 * 128 * BB];       // [k][i][b], 32 KB max

    const int total = 2 * Ci * BB;
    for (int idx = threadIdx.x; idx < total; idx += 128) {
        int b  = idx & 31;
        int ki = idx >> 5;
        int k  = (ki >= Ci) ? 1 : 0;
        int i  = ki - (k ? Ci : 0);
        float v;
        if (i < Cix) v = k ? sX1[(size_t)n * stx1 + i * BB + b]
                           : sX0[(size_t)n * stx0 + i * BB + b];
        else {
            int ih = i - Cix;
            v = k ? sH1[(size_t)n * sth1 + ih * BB + b]
                  : sH0[(size_t)n * sth0 + ih * BB + b];
        }
        s[idx] = v;
    }
    __syncthreads();

    float acc[BB];
#pragma unroll
    for (int b = 0; b < BB; b++) acc[b] = 0.f;

    const float* Wn = W + (size_t)n * 2 * Ci * 128;
    for (int k = 0; k < 2; k++) {
        const float* Wk = Wn + k * Ci * 128;
        const float* sk = s  + k * Ci * BB;
        for (int i = 0; i < Ci; i++) {
            float w = Wk[i * 128 + o];
            const float4* sp = reinterpret_cast<const float4*>(sk + i * BB);
#pragma unroll
            for (int j = 0; j < 8; j++) {
                float4 v = sp[j];
                acc[4 * j + 0] += v.x * w;
                acc[4 * j + 1] += v.y * w;
                acc[4 * j + 2] += v.z * w;
                acc[4 * j + 3] += v.w * w;
            }
        }
    }

    const float bb = bias[n * 128 + o];
    if (o < HID) {
        const float* hpart = s + Cix * BB + o * BB;   // k=0, h segment, row o
        float* zp = zh + ((size_t)n * HID + o) * BB;
#pragma unroll
        for (int b = 0; b < BB; b++) {
            float g = 1.f / (1.f + __expf(-(acc[b] + bb)));
            zp[b] = g * hpart[b];
        }
    } else {
        const int oo = o - HID;
        float* rp = rout + ((size_t)n * HID + oo) * BB;
#pragma unroll
        for (int b = 0; b < BB; b++)
            rp[b] = 1.f / (1.f + __expf(-(acc[b] + bb)));
    }
}

// ---------------------------------------------------------------------------
// Candidate apply + GRU update:
//   hc = tanh(sum_{k,i} xg[k,i,b] * Wc[n,k,i,o] + bias)
//   hnew = r * hold + (1-r) * hc
// ---------------------------------------------------------------------------
__global__ __launch_bounds__(64) void cand_apply_kernel(
    const float* __restrict__ sX0, int stx0,
    const float* __restrict__ sH0, int sth0,
    const float* __restrict__ sX1, int stx1,
    const float* __restrict__ sH1, int sth1,
    const float* __restrict__ W, const float* __restrict__ bias,
    const float* __restrict__ rbuf,
    const float* __restrict__ hold, int sthold,
    float* __restrict__ hnew, int sthnew, int Cix)
{
    const int n  = blockIdx.x;
    const int o  = threadIdx.x;             // 0..63
    const int Ci = Cix + HID;

    __shared__ float s[2 * 128 * BB];

    const int total = 2 * Ci * BB;
    for (int idx = threadIdx.x; idx < total; idx += 64) {
        int b  = idx & 31;
        int ki = idx >> 5;
        int k  = (ki >= Ci) ? 1 : 0;
        int i  = ki - (k ? Ci : 0);
        float v;
        if (i < Cix) v = k ? sX1[(size_t)n * stx1 + i * BB + b]
                           : sX0[(size_t)n * stx0 + i * BB + b];
        else {
            int ih = i - Cix;
            v = k ? sH1[(size_t)n * sth1 + ih * BB + b]
                  : sH0[(size_t)n * sth0 + ih * BB + b];
        }
        s[idx] = v;
    }
    __syncthreads();

    float acc[BB];
#pragma unroll
    for (int b = 0; b < BB; b++) acc[b] = 0.f;

    const float* Wn = W + (size_t)n * 2 * Ci * HID;
    for (int k = 0; k < 2; k++) {
        const float* Wk = Wn + k * Ci * HID;
        const float* sk = s  + k * Ci * BB;
        for (int i = 0; i < Ci; i++) {
            float w = Wk[i * HID + o];
            const float4* sp = reinterpret_cast<const float4*>(sk + i * BB);
#pragma unroll
            for (int j = 0; j < 8; j++) {
                float4 v = sp[j];
                acc[4 * j + 0] += v.x * w;
                acc[4 * j + 1] += v.y * w;
                acc[4 * j + 2] += v.z * w;
                acc[4 * j + 3] += v.w * w;
            }
        }
    }

    const float bb = bias[n * HID + o];
    const float* rp = rbuf + ((size_t)n * HID + o) * BB;
    const float* hp = hold + (size_t)n * sthold + o * BB;
    float* out = hnew + (size_t)n * sthnew + o * BB;
#pragma unroll
    for (int b = 0; b < BB; b++) {
        float hc = tanhf(acc[b] + bb);
        float r  = rp[b];
        out[b] = r * hp[b] + (1.f - r) * hc;
    }
}

// ---------------------------------------------------------------------------
// Output head: out[b,hor,n] = h2[n,:,b] . Wout[hor,:] + bout[hor]
// ---------------------------------------------------------------------------
__global__ __launch_bounds__(384) void out_kernel(
    const float* __restrict__ h2, const float* __restrict__ Wout,
    const float* __restrict__ bout, float* __restrict__ out)
{
    const int n = blockIdx.x;
    __shared__ float sh[HID * BB];
    for (int idx = threadIdx.x; idx < HID * BB; idx += 384)
        sh[idx] = h2[(size_t)n * HID * BB + idx];
    __syncthreads();

    int p = threadIdx.x;                    // 0..383 = b*12 + hor
    int b = p / HORZ, hor = p % HORZ;
    float a = bout[hor];
#pragma unroll
    for (int j = 0; j < HID; j++) a += sh[j * BB + b] * Wout[hor * HID + j];
    out[(b * HORZ + hor) * NN + n] = a;
}

// ---------------------------------------------------------------------------
// Host orchestration
// ---------------------------------------------------------------------------
static float* sym_addr(const void* symbol)
{
    void* p = nullptr;
    cudaGetSymbolAddress(&p, symbol);
    return reinterpret_cast<float*>(p);
}

extern "C" void kernel_launch(void* const* d_in, const int* in_sizes, int n_in,
                              void* d_out, int out_size)
{
    (void)in_sizes; (void)n_in; (void)out_size;
    const float* x    = (const float*)d_in[0];
    const float* E    = (const float*)d_in[1];
    const float* Wg1  = (const float*)d_in[2];
    const float* bg1  = (const float*)d_in[3];
    const float* Wc1  = (const float*)d_in[4];
    const float* bc1  = (const float*)d_in[5];
    const float* Wg2  = (const float*)d_in[6];
    const float* bg2  = (const float*)d_in[7];
    const float* Wc2  = (const float*)d_in[8];
    const float* bc2  = (const float*)d_in[9];
    const float* Wout = (const float*)d_in[10];
    const float* bout = (const float*)d_in[11];
    float* out = (float*)d_out;

    float* A    = sym_addr(g_A);
    float* xT   = sym_addr(g_xT);
    float* mx   = sym_addr(g_mx);
    float* h1   = sym_addr(g_h1);
    float* mh1  = sym_addr(g_mh1);
    float* h2   = sym_addr(g_h2);
    float* mh   = sym_addr(g_mh);
    float* zh   = sym_addr(g_zh);
    float* mzh  = sym_addr(g_mzh);
    float* rb   = sym_addr(g_r);
    float* zero = sym_addr(g_zero);
    float* wg1n = sym_addr(g_Wg1n);
    float* bg1n = sym_addr(g_bg1n);
    float* wc1n = sym_addr(g_Wc1n);
    float* bc1n = sym_addr(g_bc1n);
    float* wg2n = sym_addr(g_Wg2n);
    float* bg2n = sym_addr(g_bg2n);
    float* wc2n = sym_addr(g_Wc2n);
    float* bc2n = sym_addr(g_bc2n);

    const int HB  = HID * BB;               // 2048
    const int LD1 = TT * HB;                // 24576 (h1 / mh1 row stride)

    // ---- precompute ----
    compute_A_kernel<<<NN, 256>>>(E, A);
    transpose_x_kernel<<<(BB * TT * NN + 255) / 256, 256>>>(x, xT);

    gen_w_kernel<<<dim3((2 * 65 * 128 + 255) / 256, 32), 256>>>(Wg1, E, wg1n, 2 * 65 * 128);
    gen_w_kernel<<<dim3(1, 32), 256>>>(bg1, E, bg1n, 128);
    gen_w_kernel<<<dim3((2 * 65 * 64 + 255) / 256, 32), 256>>>(Wc1, E, wc1n, 2 * 65 * 64);
    gen_w_kernel<<<dim3(1, 32), 256>>>(bc1, E, bc1n, 64);
    gen_w_kernel<<<dim3((2 * 128 * 128) / 256, 32), 256>>>(Wg2, E, wg2n, 2 * 128 * 128);
    gen_w_kernel<<<dim3(1, 32), 256>>>(bg2, E, bg2n, 128);
    gen_w_kernel<<<dim3((2 * 128 * 64) / 256, 32), 256>>>(Wc2, E, wc2n, 2 * 128 * 64);
    gen_w_kernel<<<dim3(1, 32), 256>>>(bc2, E, bc2n, 64);

    // mixed x for layer 1 (all timesteps at once): [N, T*B]
    sgemm_f32x2<<<dim3((TT * BB) / 128, 8), 256>>>(A, xT, mx, TT * BB, TT * BB);

    // ---- layer 1 ----
    // A @ h1[t-1] is written straight into the mh1 slab (slice t-1), so the
    // per-step mixing doubles as the layer-2 input mixing; only the t=11
    // slice needs a separate GEMM after the loop.
    for (int t = 0; t < TT; t++) {
        const float *hp, *mhp, *mzhp;
        int shp, smh, smzh;
        if (t == 0) { hp = zero; shp = 0; mhp = zero; smh = 0; }
        else {
            hp = h1 + (t - 1) * HB; shp = LD1;
            float* mdst = mh1 + (t - 1) * HB;
            sgemm_f32x2<<<dim3(HB / 128, 8), 256>>>(A, hp, mdst, LD1, LD1);
            mhp = mdst; smh = LD1;
        }
        gate_apply_kernel<<<NN, 128>>>(xT + t * BB, TT * BB, hp, shp,
                                       mx + t * BB, TT * BB, mhp, smh,
                                       wg1n, bg1n, zh, rb, 1);
        if (t == 0) { mzhp = zero; smzh = 0; }
        else {
            sgemm_f32x2<<<dim3(HB / 128, 8), 256>>>(A, zh, mzh, HB, HB);
            mzhp = mzh; smzh = HB;
        }
        cand_apply_kernel<<<NN, 64>>>(xT + t * BB, TT * BB, zh, HB,
                                      mx + t * BB, TT * BB, mzhp, smzh,
                                      wc1n, bc1n, rb, hp, shp,
                                      h1 + t * HB, LD1, 1);
    }
    // missing slice: A @ h1[11] -> mh1 slice 11
    sgemm_f32x2<<<dim3(HB / 128, 8), 256>>>(A, h1 + (TT - 1) * HB,
                                            mh1 + (TT - 1) * HB, LD1, LD1);

    // ---- layer 2 ----
    for (int t = 0; t < TT; t++) {
        const float* x0 = h1  + t * HB;
        const float* x1 = mh1 + t * HB;
        const float *hp, *mhp, *mzhp;
        int shp, smh, smzh;
        if (t == 0) { hp = zero; shp = 0; mhp = zero; smh = 0; }
        else {
            hp = h2; shp = HB;
            sgemm_f32x2<<<dim3(HB / 128, 8), 256>>>(A, h2, mh, HB, HB);
            mhp = mh; smh = HB;
        }
        gate_apply_kernel<<<NN, 128>>>(x0, LD1, hp, shp,
                                       x1, LD1, mhp, smh,
                                       wg2n, bg2n, zh, rb, HID);
        if (t == 0) { mzhp = zero; smzh = 0; }
        else {
            sgemm_f32x2<<<dim3(HB / 128, 8), 256>>>(A, zh, mzh, HB, HB);
            mzhp = mzh; smzh = HB;
        }
        cand_apply_kernel<<<NN, 64>>>(x0, LD1, zh, HB,
                                      x1, LD1, mzhp, smzh,
                                      wc2n, bc2n, rb, hp, shp,
                                      h2, HB, HID);
    }

    // ---- output head ----
    out_kernel<<<NN, 384>>>(h2, Wout, bout, out);
}